// round 10
// baseline (speedup 1.0000x reference)
#include <cuda_runtime.h>
#include <cuda_bf16.h>
#include <math.h>

#define NF 6000
#define MAXJ 64
#define LTB_STRIDE 65          // 65 % 32 == 1 -> conflict-free LDS
#define NCTAS 8

// ---------------- persistent device scratch (no allocations allowed) ----------------
__device__ float          g_F[NF * 256];          // F_t[b][j] best-at-first-state (pre-dens)
__device__ unsigned char  g_bp[NF * 256];         // argmax tempo index i
__device__ float          g_chain0[NF * MAXJ];    // chain dens sum, prev-beat != 0 (e=1)
__device__ float          g_chain1[NF * MAXJ];    // chain dens sum, prev-beat == 0 (e=2)
__device__ double         g_P[3][NF + 8];         // exclusive prefix sums of dens channels
__device__ int            g_L[MAXJ], g_c[MAXJ], g_lo[MAXJ], g_w[MAXJ], g_first0[MAXJ];
__device__ float          g_LTb[MAXJ * LTB_STRIDE];
__device__ unsigned char  g_sj[8192];             // state-within-beat -> tempo j
__device__ int            g_R;                    // frames per round (min interval, capped 32)
__device__ float          g_logS;

// ---------------------------------- setup ----------------------------------
__global__ void __launch_bounds__(1024, 1)
k_setup(const float* __restrict__ act,
        const float* __restrict__ LT,
        const int*   __restrict__ first_in,
        const int*   __restrict__ ptr_in,
        int S, int J)
{
    __shared__ int sh_minL;
    __shared__ double s0[1024], s1[1024], s2[1024];
    int tid = threadIdx.x;
    int nsb = S / 4;
    if (tid == 0) { sh_minL = 1 << 30; g_logS = logf((float)S); }
    __syncthreads();

    if (tid < J) {
        int j  = tid;
        int f0 = first_in[j];
        int L  = ((j + 1 < J) ? first_in[j + 1] : nsb) - f0;
        g_first0[j] = f0;
        g_L[j] = L;
        int c = 0;
        while (c < L && ptr_in[f0 + c] != 0) c++;   // leading "beat/downbeat" positions
        g_c[j] = c;
        atomicMin(&sh_minL, L);
        // transition band (contiguous nonzero region of column j)
        int lo = 0;
        while (lo < J && LT[lo * J + j] <= -1e29f) lo++;
        int hi = J - 1;
        while (hi >= 0 && LT[hi * J + j] <= -1e29f) hi--;
        int w = hi - lo + 1;
        g_lo[j] = lo; g_w[j] = w;
        for (int k = 0; k < w; k++) g_LTb[j * LTB_STRIDE + k] = LT[(lo + k) * J + j];
        for (int p = 0; p < L; p++) g_sj[f0 + p] = (unsigned char)j;
    }
    __syncthreads();
    if (tid == 0) {
        int R = sh_minL;
        if (R > 32) R = 32;
        if (R < 1)  R = 1;
        g_R = R;
    }

    // -------- dens prefix sums in fp64 (chunked block scan) --------
    const int CH = (NF + 1023) / 1024;   // 6
    int f0 = tid * CH;
    int f1 = f0 + CH; if (f1 > NF) f1 = NF;
    double a0 = 0, a1 = 0, a2 = 0;
    for (int f = f0; f < f1; f++) {
        float ab = act[2 * f], ad = act[2 * f + 1];
        a0 += (double)logf((1.0f - ab - ad) * (1.0f / 15.0f));
        a1 += (double)logf(ab);
        a2 += (double)logf(ad);
    }
    s0[tid] = a0; s1[tid] = a1; s2[tid] = a2;
    __syncthreads();
    if (tid == 0) {
        double r0 = 0, r1 = 0, r2 = 0;
        for (int k = 0; k < 1024; k++) {
            double t0 = s0[k]; s0[k] = r0; r0 += t0;
            double t1 = s1[k]; s1[k] = r1; r1 += t1;
            double t2 = s2[k]; s2[k] = r2; r2 += t2;
        }
        g_P[0][NF] = r0; g_P[1][NF] = r1; g_P[2][NF] = r2;
    }
    __syncthreads();
    double b0 = s0[tid], b1 = s1[tid], b2 = s2[tid];
    for (int f = f0; f < f1; f++) {
        g_P[0][f] = b0; g_P[1][f] = b1; g_P[2][f] = b2;
        float ab = act[2 * f], ad = act[2 * f + 1];
        b0 += (double)logf((1.0f - ab - ad) * (1.0f / 15.0f));
        b1 += (double)logf(ab);
        b2 += (double)logf(ad);
    }
}

// -------- per (t, tempo) chain dens sums (clamped for t < L) --------
__global__ void k_chain(int J)
{
    int idx = blockIdx.x * 1024 + threadIdx.x;
    int t = idx >> 6;
    int i = idx & 63;
    if (t >= NF || i >= J) return;
    int L = g_L[i], c = g_c[i];
    int m0 = t - L;     if (m0 < 0) m0 = 0;
    int m1 = t - L + c; if (m1 < 0) m1 = 0;
    double p0t = g_P[0][t], p0m = g_P[0][m1];
    g_chain0[t * MAXJ + i] = (float)((g_P[1][m1] - g_P[1][m0]) + (p0t - p0m));
    g_chain1[t * MAXJ + i] = (float)((g_P[2][m1] - g_P[2][m0]) + (p0t - p0m));
}

// ---------------------- forward Viterbi: persistent 8-CTA cluster ----------------------
// Cross-CTA visibility: barrier.cluster.arrive has RELEASE semantics and wait has
// ACQUIRE semantics at cluster scope; readers use __ldcg (L2 = cluster coherence
// point), so no explicit __threadfence is needed.
__global__ void __cluster_dims__(NCTAS, 1, 1) __launch_bounds__(1024, 1)
k_forward(int J)
{
    __shared__ float s_LTb[MAXJ * LTB_STRIDE];
    __shared__ float s_cand[16 * 64];
    __shared__ int   s_L[MAXJ], s_lo[MAXJ], s_w[MAXJ];

    int tid = threadIdx.x;
    for (int k = tid; k < MAXJ * LTB_STRIDE; k += 1024) s_LTb[k] = g_LTb[k];
    if (tid < MAXJ) { s_L[tid] = g_L[tid]; s_lo[tid] = g_lo[tid]; s_w[tid] = g_w[tid]; }
    int   R       = g_R;
    float negLogS = -g_logS;
    __syncthreads();

    int S4     = 4 * J;
    int ng     = R * 4;
    int perCTA = (ng + NCTAS - 1) / NCTAS;
    int lg     = tid >> 6;
    int lane   = tid & 63;
    int gg     = (int)blockIdx.x * perCTA + lg;
    bool grp   = (lg < perCTA) && (gg < ng);
    int fo     = gg >> 2;            // frame offset within round
    int b      = gg & 3;             // beat
    int bprev  = (b + 3) & 3;
    const float* chainp = (bprev == 0) ? g_chain1 : g_chain0;

    for (int t0 = 0; t0 < NF; t0 += R) {
        int t   = t0 + fo;
        bool act = grp && (t < NF);

        if (act && lane < J) {       // gather candidates
            int i   = lane;
            int tau = t - s_L[i];
            float Fv = (tau >= 0) ? __ldcg(&g_F[tau * S4 + bprev * J + i]) : negLogS;
            s_cand[(lg << 6) + i] = Fv + chainp[t * MAXJ + i];
        }
        __syncthreads();

        if (act && lane < J) {       // banded max-plus reduce
            int j  = lane;
            int lo = s_lo[j], w = s_w[j];
            const float* cb = &s_cand[(lg << 6) + lo];
            const float* lb = &s_LTb[j * LTB_STRIDE];
            float best = -3.0e38f; int arg = 0;
            #pragma unroll 4
            for (int k = 0; k < w; k++) {
                float sc = cb[k] + lb[k];
                if (sc > best) { best = sc; arg = k; }
            }
            int idx = t * S4 + b * J + j;
            g_F[idx]  = best;
            g_bp[idx] = (unsigned char)(lo + arg);
        }

        asm volatile("barrier.cluster.arrive.aligned;" ::: "memory");  // release
        asm volatile("barrier.cluster.wait.aligned;"   ::: "memory");  // acquire
    }
}

// ---------------------- finalize: v_final argmax + backtrack + fill ----------------------
__global__ void __launch_bounds__(1024, 1)
k_final(const int* __restrict__ prev_last, float* __restrict__ out,
        int out_size, int J, int S)
{
    __shared__ unsigned long long s_key;
    __shared__ int   sg_t[300], sg_s[300], sg_p[300];
    __shared__ int   s_nseg;
    __shared__ float s_logp;
    __shared__ int   sL[MAXJ];
    __shared__ int   sPL[4 * MAXJ];

    int tid = threadIdx.x;
    if (tid == 0) s_key = 0ull;
    if (tid < J) sL[tid] = g_L[tid];
    if (tid < 4 * J) sPL[tid] = prev_last[tid];
    __syncthreads();

    int nsb = S / 4, S4 = 4 * J;

    // ---- v_final for every state, packed (value, first-index) argmax ----
    unsigned long long lbest = 0ull;
    for (int s = tid; s < S; s += 1024) {
        int b  = s / nsb;
        int wl = s - b * nsb;
        int j  = g_sj[wl];
        int p  = wl - g_first0[j];
        int tau0 = (NF - 1) - p;
        int cc = g_c[j]; if (cc > p + 1) cc = p + 1;
        int e  = (b == 0) ? 2 : 1;
        double sum = (g_P[e][tau0 + cc] - g_P[e][tau0]) + (g_P[0][NF] - g_P[0][tau0 + cc]);
        float v = g_F[tau0 * S4 + b * J + j] + (float)sum;
        unsigned bits = __float_as_uint(v);
        unsigned u = (bits & 0x80000000u) ? ~bits : (bits | 0x80000000u);
        unsigned long long key = ((unsigned long long)u << 32) |
                                 (unsigned long long)(0xFFFFFFFFu - (unsigned)s);
        if (key > lbest) lbest = key;
    }
    for (int o = 16; o; o >>= 1) {
        unsigned long long other = __shfl_down_sync(0xFFFFFFFFu, lbest, o);
        if (other > lbest) lbest = other;
    }
    if ((tid & 31) == 0) atomicMax(&s_key, lbest);
    __syncthreads();

    // ---- speculative pipelined backtrack (warp 0) ----
    // Successor recurrence: tf_k = tf_{k-1} - L[a_{k-1}]; a_k = bp[tf_k, b_k, a_{k-1}].
    // Candidate addresses for a_k depend only on tf_{k-1} -> loads issued one step
    // ahead of the select; the serial chain advances 2 steps per load latency.
    if (tid < 32) {
        int lane = tid;
        unsigned long long key = s_key;
        int sstar = (int)(0xFFFFFFFFu - (unsigned)(key & 0xFFFFFFFFull));
        unsigned u = (unsigned)(key >> 32);
        unsigned bits = (u & 0x80000000u) ? (u & 0x7FFFFFFFu) : ~u;
        if (lane == 0) s_logp = __uint_as_float(bits);

        int b0 = sstar / nsb;
        int wl = sstar - b0 * nsb;
        int j0 = g_sj[wl];
        int p0 = wl - g_first0[j0];
        int tf = (NF - 1) - p0;

        int n = 1;
        if (lane == 0) {
            sg_t[0] = NF - 1; sg_s[0] = sstar;
            sg_p[0] = (tf <= 0) ? (NF - 1) : p0;
        }

        if (tf > 0) {
            int x0 = lane;
            int x1 = lane + 32;
            int L0 = sL[(x0 < J) ? x0 : (J - 1)];
            int L1 = sL[(x1 < J) ? x1 : (J - 1)];
            bool v0 = (x0 < J), v1 = (x1 < J);

            // prologue: direct a_0 load + speculative P_1 issue (overlapped)
            int a_res = g_bp[tf * S4 + b0 * J + j0];              // a_0
            int b1 = (b0 + 3) & 3;
            unsigned Pin;
            {
                int r0 = tf - L0; if (r0 < 0) r0 = 0;
                int r1 = tf - L1; if (r1 < 0) r1 = 0;
                unsigned c0 = v0 ? (unsigned)g_bp[r0 * S4 + b1 * J + (v0 ? x0 : 0)] : 0u;
                unsigned c1 = v1 ? (unsigned)g_bp[r1 * S4 + b1 * J + (v1 ? x1 : 0)] : 0u;
                Pin = c0 | (c1 << 8);                              // P_1
            }

            int tf_prev = tf;      // tf_{k-1}
            int b_seg   = b0;      // beat of segment k-1
            while (true) {
                int b_k = (b_seg + 3) & 3;                         // beat of segment k
                // record segment k (defined by a_{k-1} = a_res)
                int s_end = sPL[b_seg * J + a_res];
                int t_end = tf_prev - 1;
                int Lj = sL[a_res];
                int tf_k = tf_prev - Lj;
                int p = (tf_k <= 0) ? t_end : (Lj - 1);
                if (lane == 0) { sg_t[n] = t_end; sg_s[n] = s_end; sg_p[n] = p; }
                n++;
                if (tf_k <= 0) break;

                // issue P_{k+1} candidates (addresses from tf_k only)
                int b_k1 = (b_k + 3) & 3;
                unsigned Pnew;
                {
                    int r0 = tf_k - L0; if (r0 < 0) r0 = 0;
                    int r1 = tf_k - L1; if (r1 < 0) r1 = 0;
                    unsigned c0 = v0 ? (unsigned)g_bp[r0 * S4 + b_k1 * J + (v0 ? x0 : 0)] : 0u;
                    unsigned c1 = v1 ? (unsigned)g_bp[r1 * S4 + b_k1 * J + (v1 ? x1 : 0)] : 0u;
                    Pnew = c0 | (c1 << 8);
                }

                // resolve a_k from P_k (in flight since previous iteration)
                unsigned sel = __shfl_sync(0xFFFFFFFFu, Pin, a_res & 31);
                int a_k = (a_res < 32) ? (int)(sel & 0xFFu) : (int)((sel >> 8) & 0xFFu);

                Pin = Pnew; a_res = a_k; tf_prev = tf_k; b_seg = b_k;
            }
        }
        if (lane == 0) s_nseg = n;
    }
    __syncthreads();

    // ---- parallel segment fill: path[te-k] = se-k ----
    int n    = s_nseg;
    int wid  = tid >> 5, lane = tid & 31;
    for (int m = wid; m < n; m += 32) {
        int te = sg_t[m], se = sg_s[m], p = sg_p[m];
        for (int k = lane; k <= p; k += 32) {
            int f = te - k;
            if (f >= 0 && f < out_size) out[f] = (float)(se - k);
        }
    }
    if (tid == 0 && out_size > NF) out[NF] = s_logp;
}

// ---------------------------------- launch ----------------------------------
extern "C" void kernel_launch(void* const* d_in, const int* in_sizes, int n_in,
                              void* d_out, int out_size)
{
    const float* act    = (const float*)d_in[0];   // (6000,2) f32
    const float* LT     = (const float*)d_in[1];   // (4,J,J)  f32 (beats identical)
    const int*   prevl  = (const int*)  d_in[2];   // (4,J)
    const int*   firsts = (const int*)  d_in[3];   // (4,J)
    const int*   ptr    = (const int*)  d_in[4];   // (S,)

    int S = in_sizes[4];
    int J = in_sizes[2] / 4;
    if (J > MAXJ) J = MAXJ;   // defensive

    k_setup  <<<1,   1024>>>(act, LT, firsts, ptr, S, J);
    k_chain  <<<(NF * 64 + 1023) / 1024, 1024>>>(J);
    k_forward<<<NCTAS, 1024>>>(J);
    k_final  <<<1,   1024>>>(prevl, (float*)d_out, out_size, J, S);
}

// round 13
// speedup vs baseline: 1.1569x; 1.1569x over previous
#include <cuda_runtime.h>
#include <cuda_bf16.h>
#include <math.h>

#define NF 6000
#define MAXJ 64
#define LTB_STRIDE 65          // 65 % 32 == 1 -> conflict-free LDS
#define NCTAS 8
#define GDROWS (NF + 192)      // diagonal rows: t + L_j can reach NF-1 + maxL (~109)

// ---------------- persistent device scratch (no allocations allowed) ----------------
__device__ float          g_D[GDROWS * 256];      // DIAGONAL: gD[(tau+L_j)*256 + b*64 + j]
                                                  //   = F_tau[b][j] + chain_{e(b)}[tau+L_j][j]
__device__ unsigned char  g_bp[NF * 256];         // argmax tempo index at (t, b, j)
__device__ float          g_chS0[NF * MAXJ];      // shifted chain sums, e=1 (reader bprev != 0)
__device__ float          g_chS1[NF * MAXJ];      // shifted chain sums, e=2 (reader bprev == 0)
__device__ double         g_P[3][NF + 8];         // exclusive prefix sums of dens channels
__device__ int            g_L[MAXJ], g_c[MAXJ], g_lo[MAXJ], g_w[MAXJ], g_first0[MAXJ];
__device__ float          g_LTb[MAXJ * LTB_STRIDE];
__device__ unsigned char  g_sj[8192];             // state-within-beat -> tempo j
__device__ int            g_R;                    // frames per round (min interval, capped 32)
__device__ float          g_logS;

// ---------------------------------- setup ----------------------------------
__global__ void k_setup(const float* __restrict__ act,
                        const float* __restrict__ LT,
                        const int*   __restrict__ first_in,
                        const int*   __restrict__ ptr_in,
                        int S, int J)
{
    __shared__ int sh_minL;
    __shared__ double s0[256], s1[256], s2[256];
    int tid = threadIdx.x;
    int nsb = S / 4;
    if (tid == 0) { sh_minL = 1 << 30; g_logS = logf((float)S); }
    __syncthreads();

    if (tid < J) {
        int j  = tid;
        int f0 = first_in[j];
        int L  = ((j + 1 < J) ? first_in[j + 1] : nsb) - f0;
        g_first0[j] = f0;
        g_L[j] = L;
        int c = 0;
        while (c < L && ptr_in[f0 + c] != 0) c++;   // leading "beat/downbeat" positions
        g_c[j] = c;
        atomicMin(&sh_minL, L);
        // transition band (contiguous nonzero region of column j)
        int lo = 0;
        while (lo < J && LT[lo * J + j] <= -1e29f) lo++;
        int hi = J - 1;
        while (hi >= 0 && LT[hi * J + j] <= -1e29f) hi--;
        int w = hi - lo + 1;
        g_lo[j] = lo; g_w[j] = w;
        for (int k = 0; k < w; k++) g_LTb[j * LTB_STRIDE + k] = LT[(lo + k) * J + j];
        for (int p = 0; p < L; p++) g_sj[f0 + p] = (unsigned char)j;
    }
    __syncthreads();
    if (tid == 0) {
        int R = sh_minL;
        if (R > 32) R = 32;
        if (R < 1)  R = 1;
        g_R = R;
    }

    // -------- dens prefix sums in fp64 (chunked block scan) --------
    const int CH = (NF + 255) / 256;   // 24
    int f0 = tid * CH;
    int f1 = f0 + CH; if (f1 > NF) f1 = NF;
    double a0 = 0, a1 = 0, a2 = 0;
    for (int f = f0; f < f1; f++) {
        float ab = act[2 * f], ad = act[2 * f + 1];
        a0 += (double)logf((1.0f - ab - ad) * (1.0f / 15.0f));
        a1 += (double)logf(ab);
        a2 += (double)logf(ad);
    }
    s0[tid] = a0; s1[tid] = a1; s2[tid] = a2;
    __syncthreads();
    if (tid == 0) {
        double r0 = 0, r1 = 0, r2 = 0;
        for (int k = 0; k < 256; k++) {
            double t0 = s0[k]; s0[k] = r0; r0 += t0;
            double t1 = s1[k]; s1[k] = r1; r1 += t1;
            double t2 = s2[k]; s2[k] = r2; r2 += t2;
        }
        g_P[0][NF] = r0; g_P[1][NF] = r1; g_P[2][NF] = r2;
    }
    __syncthreads();
    double b0 = s0[tid], b1 = s1[tid], b2 = s2[tid];
    for (int f = f0; f < f1; f++) {
        g_P[0][f] = b0; g_P[1][f] = b1; g_P[2][f] = b2;
        float ab = act[2 * f], ad = act[2 * f + 1];
        b0 += (double)logf((1.0f - ab - ad) * (1.0f / 15.0f));
        b1 += (double)logf(ab);
        b2 += (double)logf(ad);
    }
}

// -------- shifted chain sums (writer-side) + boundary prefill of the diagonal --------
__global__ void k_chain(int J)
{
    int idx = blockIdx.x * 1024 + threadIdx.x;
    int t = idx >> 6;
    int i = idx & 63;
    if (t >= NF || i >= J) return;
    int L = g_L[i], c = g_c[i];

    // shifted chain: value the writer at frame t (tempo i) must add; reader frame = t+L
    int tp = t + L; if (tp > NF) tp = NF;          // clamped rows are never read
    int m0 = tp - L;
    int m1 = m0 + c;
    {
        double base = g_P[0][tp] - g_P[0][m1];
        g_chS0[t * MAXJ + i] = (float)((g_P[1][m1] - g_P[1][m0]) + base);
        g_chS1[t * MAXJ + i] = (float)((g_P[2][m1] - g_P[2][m0]) + base);
    }

    // boundary prefill: reader at frame t with t < L_i has virtual writer at tau < 0
    if (t < L) {
        int n1 = t - L + c; if (n1 < 0) n1 = 0;    // n0 = 0 after clamp
        double base = g_P[0][t] - g_P[0][n1];
        float ch0 = (float)((g_P[1][n1] - g_P[1][0]) + base);
        float ch1 = (float)((g_P[2][n1] - g_P[2][0]) + base);
        float nls = -g_logS;
        g_D[t * 256 +   0 + i] = nls + ch1;        // slot beat 0 => reader bprev==0 => e=2
        g_D[t * 256 +  64 + i] = nls + ch0;
        g_D[t * 256 + 128 + i] = nls + ch0;
        g_D[t * 256 + 192 + i] = nls + ch0;
    }
}

// ---------------------- forward Viterbi: persistent 8-CTA cluster ----------------------
// Diagonal layout makes the latency-critical gather a single coalesced load:
//   reader (t,b):  cand_i = gD[t*256 + bprev*64 + i]          (2 cache lines)
//   writer (t,b,j): gD[(t+L_j)*256 + b*64 + j] = best + chS   (scattered, fire-and-forget)
// Same-round rows never alias (writes hit rows >= t0+R, reads rows <= t0+R-1).
// barrier.cluster.arrive/wait provide release/acquire at cluster scope; reads use
// __ldcg (L2 = cluster coherence point).
__global__ void __cluster_dims__(NCTAS, 1, 1) __launch_bounds__(1024, 1)
k_forward(int J)
{
    __shared__ float s_LTb[MAXJ * LTB_STRIDE];
    __shared__ float s_cand[16 * 64];
    __shared__ int   s_L[MAXJ], s_lo[MAXJ], s_w[MAXJ];

    int tid = threadIdx.x;
    for (int k = tid; k < MAXJ * LTB_STRIDE; k += 1024) s_LTb[k] = g_LTb[k];
    if (tid < MAXJ) { s_L[tid] = g_L[tid]; s_lo[tid] = g_lo[tid]; s_w[tid] = g_w[tid]; }
    int R = g_R;
    __syncthreads();

    int ng     = R * 4;
    int perCTA = (ng + NCTAS - 1) / NCTAS;
    int lg     = tid >> 6;
    int lane   = tid & 63;
    int gg     = (int)blockIdx.x * perCTA + lg;
    bool grp   = (lg < perCTA) && (gg < ng);
    int fo     = gg >> 2;            // frame offset within round
    int b      = gg & 3;             // beat
    int bprev  = (b + 3) & 3;
    const float* chSp = (b == 0) ? g_chS1 : g_chS0;   // writer-side chain (keyed by OWN beat)

    int Lj = 0, lo = 0, w = 0;
    if (lane < J) { Lj = s_L[lane]; lo = s_lo[lane]; w = s_w[lane]; }
    const float* lb = &s_LTb[lane * LTB_STRIDE];

    for (int t0 = 0; t0 < NF; t0 += R) {
        int t    = t0 + fo;
        bool act = grp && (t < NF) && (lane < J);
        float chv = 0.0f;

        if (act) {
            chv = chSp[t * MAXJ + lane];                          // coalesced
            s_cand[(lg << 6) + lane] = __ldcg(&g_D[t * 256 + bprev * 64 + lane]); // coalesced
        }
        __syncthreads();

        if (act) {                    // banded max-plus reduce
            const float* cb = &s_cand[(lg << 6) + lo];
            float best = -3.0e38f; int arg = 0;
            #pragma unroll 4
            for (int k = 0; k < w; k++) {
                float sc = cb[k] + lb[k];
                if (sc > best) { best = sc; arg = k; }
            }
            g_D[(t + Lj) * 256 + b * 64 + lane] = best + chv;     // scattered store
            g_bp[t * 256 + b * 64 + lane] = (unsigned char)(lo + arg);  // coalesced
        }

        asm volatile("barrier.cluster.arrive.aligned;" ::: "memory");  // release
        asm volatile("barrier.cluster.wait.aligned;"   ::: "memory");  // acquire
    }
}

// ---------------------- finalize: v_final argmax + backtrack + fill ----------------------
__global__ void __launch_bounds__(1024, 1)
k_final(const int* __restrict__ prev_last, float* __restrict__ out,
        int out_size, int J, int S)
{
    __shared__ unsigned long long s_key;
    __shared__ int   sg_t[300], sg_s[300], sg_p[300];
    __shared__ int   s_nseg;
    __shared__ float s_logp;
    __shared__ int   sL[MAXJ];
    __shared__ int   sPL[4 * MAXJ];

    int tid = threadIdx.x;
    if (tid == 0) s_key = 0ull;
    if (tid < J) sL[tid] = g_L[tid];
    if (tid < 4 * J) sPL[tid] = prev_last[tid];
    __syncthreads();

    int nsb = S / 4;

    // ---- v_final for every state, packed (value, first-index) argmax ----
    // F_tau[b][j] = gD[(tau+L_j)*256 + b*64 + j] - chS_{e(b)}[tau*64 + j]
    unsigned long long lbest = 0ull;
    for (int s = tid; s < S; s += 1024) {
        int b  = s / nsb;
        int wl = s - b * nsb;
        int j  = g_sj[wl];
        int p  = wl - g_first0[j];
        int tau0 = (NF - 1) - p;
        int Lj = sL[j];
        float chs = (b == 0) ? g_chS1[tau0 * MAXJ + j] : g_chS0[tau0 * MAXJ + j];
        float F = g_D[(tau0 + Lj) * 256 + b * 64 + j] - chs;
        int cc = g_c[j]; if (cc > p + 1) cc = p + 1;
        int e  = (b == 0) ? 2 : 1;
        double sum = (g_P[e][tau0 + cc] - g_P[e][tau0]) + (g_P[0][NF] - g_P[0][tau0 + cc]);
        float v = F + (float)sum;
        unsigned bits = __float_as_uint(v);
        unsigned u = (bits & 0x80000000u) ? ~bits : (bits | 0x80000000u);
        unsigned long long key = ((unsigned long long)u << 32) |
                                 (unsigned long long)(0xFFFFFFFFu - (unsigned)s);
        if (key > lbest) lbest = key;
    }
    for (int o = 16; o; o >>= 1) {
        unsigned long long other = __shfl_down_sync(0xFFFFFFFFu, lbest, o);
        if (other > lbest) lbest = other;
    }
    if ((tid & 31) == 0) atomicMax(&s_key, lbest);
    __syncthreads();

    // ---- serial jump-chain backtrack: ONE dependent L2 load per segment ----
    if (tid == 0) {
        unsigned long long key = s_key;
        int sstar = (int)(0xFFFFFFFFu - (unsigned)(key & 0xFFFFFFFFull));
        unsigned u = (unsigned)(key >> 32);
        unsigned bits = (u & 0x80000000u) ? (u & 0x7FFFFFFFu) : ~u;
        s_logp = __uint_as_float(bits);

        int b  = sstar / nsb;
        int wl = sstar - b * nsb;
        int j  = g_sj[wl];
        int p  = wl - g_first0[j];
        int t  = NF - 1, s = sstar, n = 0;
        while (true) {
            int tf = t - p;
            if (tf <= 0) { sg_t[n] = t; sg_s[n] = s; sg_p[n] = t; n++; break; }
            sg_t[n] = t; sg_s[n] = s; sg_p[n] = p; n++;
            int a = g_bp[tf * 256 + b * 64 + j];     // the only global dependency
            s = sPL[b * MAXJ ? 0 : 0];               // placeholder avoided below
            s = sPL[b * J + a];
            t = tf - 1;
            b = (b + 3) & 3;
            j = a;
            p = sL[a] - 1;
        }
        s_nseg = n;
    }
    __syncthreads();

    // ---- parallel segment fill: path[te-k] = se-k ----
    int n    = s_nseg;
    int wid  = tid >> 5, lane = tid & 31;
    for (int m = wid; m < n; m += 32) {
        int te = sg_t[m], se = sg_s[m], p = sg_p[m];
        for (int k = lane; k <= p; k += 32) {
            int f = te - k;
            if (f >= 0 && f < out_size) out[f] = (float)(se - k);
        }
    }
    if (tid == 0 && out_size > NF) out[NF] = s_logp;
}

// ---------------------------------- launch ----------------------------------
extern "C" void kernel_launch(void* const* d_in, const int* in_sizes, int n_in,
                              void* d_out, int out_size)
{
    const float* act    = (const float*)d_in[0];   // (6000,2) f32
    const float* LT     = (const float*)d_in[1];   // (4,J,J)  f32 (beats identical)
    const int*   prevl  = (const int*)  d_in[2];   // (4,J)
    const int*   firsts = (const int*)  d_in[3];   // (4,J)
    const int*   ptr    = (const int*)  d_in[4];   // (S,)

    int S = in_sizes[4];
    int J = in_sizes[2] / 4;
    if (J > MAXJ) J = MAXJ;   // defensive

    k_setup  <<<1,   256 >>>(act, LT, firsts, ptr, S, J);
    k_chain  <<<(NF * 64 + 1023) / 1024, 1024>>>(J);
    k_forward<<<NCTAS, 1024>>>(J);
    k_final  <<<1,   1024>>>(prevl, (float*)d_out, out_size, J, S);
}

// round 15
// speedup vs baseline: 1.2227x; 1.0569x over previous
#include <cuda_runtime.h>
#include <cuda_bf16.h>
#include <math.h>

#define NF 6000
#define MAXJ 64
#define LTB_STRIDE 65          // 65 % 32 == 1 -> conflict-free LDS
#define NCTAS_F 28             // forward CTAs (1 per SM, all co-resident: 28 << 148)
#define FWD_THREADS 384        // 6 groups of 64 lanes; ceil(max ng=128 / 28) = 5 <= 6
#define GDROWS (NF + 192)      // diagonal rows: t + L_j can reach NF-1 + maxL (~109)

// ---------------- persistent device scratch (no allocations allowed) ----------------
__device__ float          g_D[GDROWS * 256];      // DIAGONAL: gD[(tau+L_j)*256 + b*64 + j]
                                                  //   = F_tau[b][j] + chain_{e(b)}[tau+L_j][j]
__device__ unsigned char  g_bp[NF * 256];         // argmax tempo index at (t, b, j)
__device__ float          g_chS0[NF * MAXJ];      // shifted chain sums, e=1 (writer beat != 0)
__device__ float          g_chS1[NF * MAXJ];      // shifted chain sums, e=2 (writer beat == 0)
__device__ double         g_P[3][NF + 8];         // exclusive prefix sums of dens channels
__device__ int            g_L[MAXJ], g_c[MAXJ], g_lo[MAXJ], g_w[MAXJ], g_first0[MAXJ];
__device__ float          g_LTb[MAXJ * LTB_STRIDE];
__device__ unsigned char  g_sj[8192];             // state-within-beat -> tempo j
__device__ int            g_R;                    // frames per round (min interval, capped 32)
__device__ float          g_logS;
__device__ unsigned int   g_ctr;                  // monotonic grid barrier counter

// ---------------------------------- setup ----------------------------------
__global__ void k_setup(const float* __restrict__ act,
                        const float* __restrict__ LT,
                        const int*   __restrict__ first_in,
                        const int*   __restrict__ ptr_in,
                        int S, int J)
{
    __shared__ int sh_minL;
    __shared__ double s0[256], s1[256], s2[256];
    int tid = threadIdx.x;
    int nsb = S / 4;
    if (tid == 0) { sh_minL = 1 << 30; g_logS = logf((float)S); g_ctr = 0u; }
    __syncthreads();

    if (tid < J) {
        int j  = tid;
        int f0 = first_in[j];
        int L  = ((j + 1 < J) ? first_in[j + 1] : nsb) - f0;
        g_first0[j] = f0;
        g_L[j] = L;
        int c = 0;
        while (c < L && ptr_in[f0 + c] != 0) c++;   // leading "beat/downbeat" positions
        g_c[j] = c;
        atomicMin(&sh_minL, L);
        // transition band (contiguous nonzero region of column j)
        int lo = 0;
        while (lo < J && LT[lo * J + j] <= -1e29f) lo++;
        int hi = J - 1;
        while (hi >= 0 && LT[hi * J + j] <= -1e29f) hi--;
        int w = hi - lo + 1;
        g_lo[j] = lo; g_w[j] = w;
        for (int k = 0; k < w; k++) g_LTb[j * LTB_STRIDE + k] = LT[(lo + k) * J + j];
        for (int p = 0; p < L; p++) g_sj[f0 + p] = (unsigned char)j;
    }
    __syncthreads();
    if (tid == 0) {
        int R = sh_minL;
        if (R > 32) R = 32;
        if (R < 1)  R = 1;
        g_R = R;
    }

    // -------- dens prefix sums in fp64 (chunked block scan) --------
    const int CH = (NF + 255) / 256;   // 24
    int f0 = tid * CH;
    int f1 = f0 + CH; if (f1 > NF) f1 = NF;
    double a0 = 0, a1 = 0, a2 = 0;
    for (int f = f0; f < f1; f++) {
        float ab = act[2 * f], ad = act[2 * f + 1];
        a0 += (double)logf((1.0f - ab - ad) * (1.0f / 15.0f));
        a1 += (double)logf(ab);
        a2 += (double)logf(ad);
    }
    s0[tid] = a0; s1[tid] = a1; s2[tid] = a2;
    __syncthreads();
    if (tid == 0) {
        double r0 = 0, r1 = 0, r2 = 0;
        for (int k = 0; k < 256; k++) {
            double t0 = s0[k]; s0[k] = r0; r0 += t0;
            double t1 = s1[k]; s1[k] = r1; r1 += t1;
            double t2 = s2[k]; s2[k] = r2; r2 += t2;
        }
        g_P[0][NF] = r0; g_P[1][NF] = r1; g_P[2][NF] = r2;
    }
    __syncthreads();
    double b0 = s0[tid], b1 = s1[tid], b2 = s2[tid];
    for (int f = f0; f < f1; f++) {
        g_P[0][f] = b0; g_P[1][f] = b1; g_P[2][f] = b2;
        float ab = act[2 * f], ad = act[2 * f + 1];
        b0 += (double)logf((1.0f - ab - ad) * (1.0f / 15.0f));
        b1 += (double)logf(ab);
        b2 += (double)logf(ad);
    }
}

// -------- shifted chain sums (writer-side) + boundary prefill of the diagonal --------
__global__ void k_chain(int J)
{
    int idx = blockIdx.x * 1024 + threadIdx.x;
    int t = idx >> 6;
    int i = idx & 63;
    if (t >= NF || i >= J) return;
    int L = g_L[i], c = g_c[i];

    // shifted chain: value the writer at frame t (tempo i) must add; reader frame = t+L
    int tp = t + L; if (tp > NF) tp = NF;          // clamped rows are never read
    int m0 = tp - L;
    int m1 = m0 + c;
    {
        double base = g_P[0][tp] - g_P[0][m1];
        g_chS0[t * MAXJ + i] = (float)((g_P[1][m1] - g_P[1][m0]) + base);
        g_chS1[t * MAXJ + i] = (float)((g_P[2][m1] - g_P[2][m0]) + base);
    }

    // boundary prefill: reader at frame t with t < L_i has virtual writer at tau < 0
    if (t < L) {
        int n1 = t - L + c; if (n1 < 0) n1 = 0;    // n0 = 0 after clamp
        double base = g_P[0][t] - g_P[0][n1];
        float ch0 = (float)((g_P[1][n1] - g_P[1][0]) + base);
        float ch1 = (float)((g_P[2][n1] - g_P[2][0]) + base);
        float nls = -g_logS;
        g_D[t * 256 +   0 + i] = nls + ch1;        // slot beat 0 => reader bprev==0 => e=2
        g_D[t * 256 +  64 + i] = nls + ch0;
        g_D[t * 256 + 128 + i] = nls + ch0;
        g_D[t * 256 + 192 + i] = nls + ch0;
    }
}

// ---------------------- forward Viterbi: 28 persistent CTAs + release/acquire barrier ----
// Inner structure identical to the proven cluster version: 64-lane groups, __syncthreads
// between gather and reduce. Only the cross-CTA sync changed:
//   arrive:  __threadfence -> __syncthreads -> tid0: red.release.gpu.global.add
//   depart:  tid0 spins on ld.acquire.gpu.global until ctr >= round*NCTAS_F -> __syncthreads
// release/acquire gives a formal happens-before edge from writer stores to reader loads.
// All 28 CTAs are wave-1 resident (grid << 148 SMs), so the spin cannot deadlock.
__global__ void __launch_bounds__(FWD_THREADS, 1)
k_forward(int J)
{
    __shared__ float s_LTb[MAXJ * LTB_STRIDE];
    __shared__ float s_cand[(FWD_THREADS / 64) * 64];
    __shared__ int   s_L[MAXJ], s_lo[MAXJ], s_w[MAXJ];

    int tid = threadIdx.x;
    for (int k = tid; k < MAXJ * LTB_STRIDE; k += FWD_THREADS) s_LTb[k] = g_LTb[k];
    if (tid < MAXJ) { s_L[tid] = g_L[tid]; s_lo[tid] = g_lo[tid]; s_w[tid] = g_w[tid]; }
    int R = g_R;
    __syncthreads();

    int ng     = R * 4;
    int perCTA = (ng + NCTAS_F - 1) / NCTAS_F;
    int lg     = tid >> 6;
    int lane   = tid & 63;
    int gg     = (int)blockIdx.x * perCTA + lg;
    bool grp   = (lg < perCTA) && (gg < ng);
    int fo     = gg >> 2;            // frame offset within round
    int b      = gg & 3;             // beat
    int bprev  = (b + 3) & 3;
    const float* chSp = (b == 0) ? g_chS1 : g_chS0;   // writer-side chain (keyed by OWN beat)

    int Lj = 0, lo = 0, w = 0;
    if (lane < J) { Lj = s_L[lane]; lo = s_lo[lane]; w = s_w[lane]; }
    const float* lb = &s_LTb[lane * LTB_STRIDE];

    unsigned int round = 1u;
    for (int t0 = 0; t0 < NF; t0 += R, round++) {
        int t    = t0 + fo;
        bool act = grp && (t < NF) && (lane < J);
        float chv = 0.0f;

        if (act) {
            chv = chSp[t * MAXJ + lane];                          // coalesced
            s_cand[(lg << 6) + lane] = __ldcg(&g_D[t * 256 + bprev * 64 + lane]); // coalesced
        }
        __syncthreads();

        if (act) {                    // banded max-plus reduce
            const float* cb = &s_cand[(lg << 6) + lo];
            float best = -3.0e38f; int arg = 0;
            #pragma unroll 4
            for (int k = 0; k < w; k++) {
                float sc = cb[k] + lb[k];
                if (sc > best) { best = sc; arg = k; }
            }
            g_D[(t + Lj) * 256 + b * 64 + lane] = best + chv;     // scattered store
            g_bp[t * 256 + b * 64 + lane] = (unsigned char)(lo + arg);  // coalesced
        }

        // ---- grid-wide round barrier (release/acquire) ----
        __threadfence();                       // drain my stores to device scope
        __syncthreads();                       // all warps' fences precede the arrive
        if (tid == 0) {
            asm volatile("red.release.gpu.global.add.u32 [%0], 1;"
                         :: "l"(&g_ctr) : "memory");
            unsigned int target = round * NCTAS_F;
            unsigned int v;
            do {
                asm volatile("ld.acquire.gpu.global.u32 %0, [%1];"
                             : "=r"(v) : "l"(&g_ctr) : "memory");
            } while (v < target);
        }
        __syncthreads();                       // publish the acquire to the whole CTA
    }
}

// ---------------------- finalize: v_final argmax + backtrack + fill ----------------------
__global__ void __launch_bounds__(1024, 1)
k_final(const int* __restrict__ prev_last, float* __restrict__ out,
        int out_size, int J, int S)
{
    __shared__ unsigned long long s_key;
    __shared__ int   sg_t[300], sg_s[300], sg_p[300];
    __shared__ int   s_nseg;
    __shared__ float s_logp;
    __shared__ int   sL[MAXJ];
    __shared__ int   sPL[4 * MAXJ];

    int tid = threadIdx.x;
    if (tid == 0) s_key = 0ull;
    if (tid < J) sL[tid] = g_L[tid];
    if (tid < 4 * J) sPL[tid] = prev_last[tid];
    __syncthreads();

    int nsb = S / 4;

    // ---- v_final for every state, packed (value, first-index) argmax ----
    // F_tau[b][j] = gD[(tau+L_j)*256 + b*64 + j] - chS_{e(b)}[tau*64 + j]
    unsigned long long lbest = 0ull;
    for (int s = tid; s < S; s += 1024) {
        int b  = s / nsb;
        int wl = s - b * nsb;
        int j  = g_sj[wl];
        int p  = wl - g_first0[j];
        int tau0 = (NF - 1) - p;
        int Lj = sL[j];
        float chs = (b == 0) ? g_chS1[tau0 * MAXJ + j] : g_chS0[tau0 * MAXJ + j];
        float F = g_D[(tau0 + Lj) * 256 + b * 64 + j] - chs;
        int cc = g_c[j]; if (cc > p + 1) cc = p + 1;
        int e  = (b == 0) ? 2 : 1;
        double sum = (g_P[e][tau0 + cc] - g_P[e][tau0]) + (g_P[0][NF] - g_P[0][tau0 + cc]);
        float v = F + (float)sum;
        unsigned bits = __float_as_uint(v);
        unsigned u = (bits & 0x80000000u) ? ~bits : (bits | 0x80000000u);
        unsigned long long key = ((unsigned long long)u << 32) |
                                 (unsigned long long)(0xFFFFFFFFu - (unsigned)s);
        if (key > lbest) lbest = key;
    }
    for (int o = 16; o; o >>= 1) {
        unsigned long long other = __shfl_down_sync(0xFFFFFFFFu, lbest, o);
        if (other > lbest) lbest = other;
    }
    if ((tid & 31) == 0) atomicMax(&s_key, lbest);
    __syncthreads();

    // ---- serial jump-chain backtrack: ONE dependent L2 load per segment ----
    if (tid == 0) {
        unsigned long long key = s_key;
        int sstar = (int)(0xFFFFFFFFu - (unsigned)(key & 0xFFFFFFFFull));
        unsigned u = (unsigned)(key >> 32);
        unsigned bits = (u & 0x80000000u) ? (u & 0x7FFFFFFFu) : ~u;
        s_logp = __uint_as_float(bits);

        int b  = sstar / nsb;
        int wl = sstar - b * nsb;
        int j  = g_sj[wl];
        int p  = wl - g_first0[j];
        int t  = NF - 1, s = sstar, n = 0;
        while (true) {
            int tf = t - p;
            if (tf <= 0) { sg_t[n] = t; sg_s[n] = s; sg_p[n] = t; n++; break; }
            sg_t[n] = t; sg_s[n] = s; sg_p[n] = p; n++;
            int a = g_bp[tf * 256 + b * 64 + j];     // the only global dependency
            s = sPL[b * J + a];
            t = tf - 1;
            b = (b + 3) & 3;
            j = a;
            p = sL[a] - 1;
        }
        s_nseg = n;
    }
    __syncthreads();

    // ---- parallel segment fill: path[te-k] = se-k ----
    int n    = s_nseg;
    int wid  = tid >> 5, lane = tid & 31;
    for (int m = wid; m < n; m += 32) {
        int te = sg_t[m], se = sg_s[m], p = sg_p[m];
        for (int k = lane; k <= p; k += 32) {
            int f = te - k;
            if (f >= 0 && f < out_size) out[f] = (float)(se - k);
        }
    }
    if (tid == 0 && out_size > NF) out[NF] = s_logp;
}

// ---------------------------------- launch ----------------------------------
extern "C" void kernel_launch(void* const* d_in, const int* in_sizes, int n_in,
                              void* d_out, int out_size)
{
    const float* act    = (const float*)d_in[0];   // (6000,2) f32
    const float* LT     = (const float*)d_in[1];   // (4,J,J)  f32 (beats identical)
    const int*   prevl  = (const int*)  d_in[2];   // (4,J)
    const int*   firsts = (const int*)  d_in[3];   // (4,J)
    const int*   ptr    = (const int*)  d_in[4];   // (S,)

    int S = in_sizes[4];
    int J = in_sizes[2] / 4;
    if (J > MAXJ) J = MAXJ;   // defensive

    k_setup  <<<1,   256 >>>(act, LT, firsts, ptr, S, J);
    k_chain  <<<(NF * 64 + 1023) / 1024, 1024>>>(J);
    k_forward<<<NCTAS_F, FWD_THREADS>>>(J);
    k_final  <<<1,   1024>>>(prevl, (float*)d_out, out_size, J, S);
}